// round 14
// baseline (speedup 1.0000x reference)
#include <cuda_runtime.h>
#include <cuda_bf16.h>
#include <cstdint>

// Problem constants (fixed by the dataset)
#define T_TOK   16384
#define N_EXP   16
#define DIM     2048
#define CAP     2048
#define SLOTS   (N_EXP * CAP)           // 32768
#define OUT_MAIN ((size_t)SLOTS * DIM)  // 67,108,864 floats
#define ROW4    (DIM / 4)               // 512 float4 per row

#define CHUNKS  64
#define CHTOK   256                     // tokens per index chunk (== blockDim)
#define FILLB   128                     // fill worker blocks (ids CHUNKS..CHUNKS+FILLB)
#define GRID    1184                    // 148 SMs x 8 blocks — co-residency by construction

// Device scratch (no allocs allowed)
__device__ int      g_cnt [N_EXP * CHUNKS];  // per-expert per-chunk hit counts (4KB, L2-hot)
__device__ int      g_meta[T_TOK];           // per-token packed: 2 x 16b halves (rank<<4)|e
__device__ unsigned g_bar;                   // arrive(lo16)/depart(hi16) barrier word

// ---------------------------------------------------------------------------
// Single persistent kernel.
//   Phase 1 (blocks 0..63): count + chunk-local rank (no global sync needed
//           for the math — consumers reduce g_cnt themselves).
//   Grid barrier: all 1184 blocks are guaranteed co-resident
//           (__launch_bounds__(256,8): regs<=32, smem ~600B, 2048thr/SM
//            -> 8 blocks/SM -> 148*8 = 1184 = gridDim). Arrive/depart word
//           with last-departer reset: safe under graph replay (proven R10).
//   Phase 2: blocks 64..191 zero the per-expert tails + emit loads;
//            ALL blocks run the persistent token-copy loop.
// ---------------------------------------------------------------------------
__global__ __launch_bounds__(256, 8)
void moe_kernel(const float4* __restrict__ in4,
                const float*  __restrict__ score,
                const int4*   __restrict__ hm4,
                float4* __restrict__ out4,
                float*  __restrict__ out, long long out_size)
{
    const int bid  = blockIdx.x;
    const int tid  = threadIdx.x;
    const int lane = tid & 31;
    const int wid  = tid >> 5;           // 0..7

    __shared__ int   s_cnt[8][N_EXP];
    __shared__ int   s_dst[2];
    __shared__ float s_g[2];
    __shared__ int   s_load;

    // ======================= PHASE 1: INDEX (blocks 0..63) =================
    if (bid < CHUNKS) {
        const int c = bid;
        const int t = c * CHTOK + tid;
        const unsigned lt = (1u << lane) - 1u;

        int4 m[4];
        #pragma unroll
        for (int i = 0; i < 4; i++) m[i] = hm4[(size_t)t * 4 + i];
        const int* v = (const int*)m;

        unsigned bits = 0;
        #pragma unroll
        for (int e = 0; e < N_EXP; e++) bits |= (v[e] > 0 ? 1u : 0u) << e;

        int      k = 0;
        int      e_sel[2] = {-1, -1};
        unsigned b_sel[2] = {0, 0};
        #pragma unroll
        for (int e = 0; e < N_EXP; e++) {
            unsigned ball = __ballot_sync(0xffffffffu, (bits >> e) & 1u);
            if (lane == 0) s_cnt[wid][e] = __popc(ball);
            if (((bits >> e) & 1u) && k < 2) { e_sel[k] = e; b_sel[k] = ball; k++; }
        }
        __syncthreads();

        if (tid < N_EXP) {
            int sum = 0;
            #pragma unroll
            for (int w = 0; w < 8; w++) sum += s_cnt[w][tid];
            g_cnt[tid * CHUNKS + c] = sum;
        }

        unsigned meta = 0xFFFFFFFFu;
        #pragma unroll
        for (int j = 0; j < 2; j++) {
            unsigned h = 0xFFFFu;
            if (j < k) {
                const int e = e_sel[j];
                int woff = 0;
                #pragma unroll
                for (int w = 0; w < 8; w++) if (w < wid) woff += s_cnt[w][e];
                const int rank = woff + __popc(b_sel[j] & lt);   // < 256
                h = ((unsigned)rank << 4) | (unsigned)e;
            }
            meta = (meta & ~(0xFFFFu << (16 * j))) | (h << (16 * j));
        }
        g_meta[t] = (int)meta;
        __threadfence();                  // publish before barrier arrive
        __syncthreads();
    }

    // ======================= GRID BARRIER (all 1184 blocks) ================
    if (tid == 0) {
        atomicAdd(&g_bar, 1u);                          // arrive (low half)
        volatile unsigned* p = &g_bar;
        while ((*p & 0xFFFFu) < GRID) __nanosleep(60);  // all arrived
        unsigned prev = atomicAdd(&g_bar, 0x10000u);    // depart (high half)
        if ((prev >> 16) == GRID - 1)                   // last one out:
            atomicExch(&g_bar, 0u);                     //   reset for replay
    }
    __syncthreads();

    // ======================= PHASE 2a: TAIL FILL (blocks 64..191) ==========
    if (bid >= CHUNKS && bid < CHUNKS + FILLB) {
        const int f = bid - CHUNKS;
        const int e = f >> 3;
        const int y = f & 7;

        if (tid < 32) {
            int part = __ldcg(&g_cnt[e * CHUNKS + tid]) +
                       __ldcg(&g_cnt[e * CHUNKS + tid + 32]);
            #pragma unroll
            for (int o = 16; o >= 1; o >>= 1)
                part += __shfl_down_sync(0xffffffffu, part, o);
            if (tid == 0) {
                const int load = part < CAP ? part : CAP;
                s_load = load;
                if (y == 0 && out_size >= (long long)(OUT_MAIN + N_EXP))
                    out[OUT_MAIN + e] = (float)load;
            }
        }
        __syncthreads();
        const int load = s_load;
        const float4 z = make_float4(0.f, 0.f, 0.f, 0.f);
        for (int r = load + y; r < CAP; r += 8) {
            float4* o = out4 + (size_t)(e * CAP + r) * ROW4;
            __stcs(o + tid, z);
            __stcs(o + tid + 256, z);
        }
        __syncthreads();
    }

    // ======================= PHASE 2b: TOKEN LOOP (all blocks) =============
    for (int t = bid; t < T_TOK; t += GRID) {
        const int c = t >> 8;             // chunk of this token (CHTOK=256)

        // Issue the streaming row read first; resolution overlaps its latency.
        const float4* __restrict__ r = in4 + (size_t)t * ROW4;
        float4 a = __ldcs(r + tid);
        float4 b = __ldcs(r + tid + 256);

        const int meta = __ldcg(&g_meta[t]);
        if (tid < 64) {
            const int j  = tid >> 5;      // assignment 0 / 1
            const int ln = tid & 31;
            const unsigned h = ((unsigned)meta >> (16 * j)) & 0xFFFFu;
            int   dst = -1;
            float g   = 0.0f;
            if (h != 0xFFFFu) {
                const int e    = (int)(h & 15u);
                const int rank = (int)(h >> 4);
                int part = 0;
                if (ln < c)      part += __ldcg(&g_cnt[e * CHUNKS + ln]);
                if (ln + 32 < c) part += __ldcg(&g_cnt[e * CHUNKS + ln + 32]);
                #pragma unroll
                for (int o = 16; o >= 1; o >>= 1)
                    part += __shfl_down_sync(0xffffffffu, part, o);
                if (ln == 0) {
                    const int pos = part + rank;
                    if (pos < CAP) dst = e * CAP + pos;
                    g = __ldg(&score[t * N_EXP + e]);
                }
            }
            if (ln == 0) { s_dst[j] = dst; s_g[j] = g; }
        }
        __syncthreads();

        const int   d0 = s_dst[0];
        const int   d1 = s_dst[1];
        const float g0 = s_g[0];
        const float g1 = s_g[1];

        if (d0 >= 0) {
            float4* o = out4 + (size_t)d0 * ROW4;
            __stcs(o + tid,       make_float4(a.x * g0, a.y * g0, a.z * g0, a.w * g0));
            __stcs(o + tid + 256, make_float4(b.x * g0, b.y * g0, b.z * g0, b.w * g0));
        }
        if (d1 >= 0) {
            float4* o = out4 + (size_t)d1 * ROW4;
            __stcs(o + tid,       make_float4(a.x * g1, a.y * g1, a.z * g1, a.w * g1));
            __stcs(o + tid + 256, make_float4(b.x * g1, b.y * g1, b.z * g1, b.w * g1));
        }
        __syncthreads();                  // protect s_dst/s_g reuse next iter
    }
}

extern "C" void kernel_launch(void* const* d_in, const int* in_sizes, int n_in,
                              void* d_out, int out_size)
{
    const float* in_flow  = (const float*)d_in[0];   // [T, D] f32
    const int*   hot_mask = (const int*)  d_in[1];   // [T, E] i32
    const float* score    = (const float*)d_in[2];   // [T, E] f32
    float*       out      = (float*)d_out;

    moe_kernel<<<GRID, 256>>>((const float4*)in_flow, score,
                              (const int4*)hot_mask,
                              (float4*)out, out, (long long)out_size);
}

// round 15
// speedup vs baseline: 1.1655x; 1.1655x over previous
#include <cuda_runtime.h>
#include <cuda_bf16.h>
#include <cstdint>

// Problem constants (fixed by the dataset)
#define T_TOK   16384
#define N_EXP   16
#define DIM     2048
#define CAP     2048
#define SLOTS   (N_EXP * CAP)           // 32768
#define OUT_MAIN ((size_t)SLOTS * DIM)  // 67,108,864 floats
#define ROW4    (DIM / 4)               // 512 float4 per row

#define CHUNKS  64
#define CHTOK   256                     // tokens per index chunk (== blockDim)
#define IDXB    CHUNKS                  // idx blocks: bid 0..63 (wave-1 by dispatch order)
#define FILLB   128                     // fill blocks at the END of the grid
#define GRID_T  (IDXB + T_TOK + FILLB)  // 16576 total blocks

// Device scratch (no allocs allowed)
__device__ int      g_cnt [N_EXP * CHUNKS];  // per-expert per-chunk counts (4KB, L2-hot)
__device__ int      g_meta[T_TOK];           // per-token packed: 2 x 16b (rank<<4)|e, 0xFFFF=none
__device__ unsigned g_done;                  // idx completion counter (reaches IDXB)
__device__ unsigned g_fin;                   // block completion counter (reaches GRID_T)

// ---------------------------------------------------------------------------
// ONE kernel, three block roles, NO persistent loop (keeps full cross-block
// MLP that R14 lost):
//   bid in [0, 64):        idx — counts + chunk-local ranks, then g_done++.
//   bid in [64, 64+16384): token — issue row loads + score prefetch FIRST,
//                          then one flag check (wave-1 blocks hide the idx
//                          phase under their own DRAM latency; later blocks
//                          see the flag already set).
//   bid in [last 128):     fill — per-expert tail zeroing + loads output.
// Replay-safe reset: every block bumps g_fin at exit; the last one (all
// blocks past their flag check by definition) zeroes g_done then g_fin.
// ---------------------------------------------------------------------------
__global__ __launch_bounds__(256)
void moe_kernel(const float4* __restrict__ in4,
                const float*  __restrict__ score,
                const int4*   __restrict__ hm4,
                float4* __restrict__ out4,
                float*  __restrict__ out, long long out_size)
{
    const int bid  = blockIdx.x;
    const int tid  = threadIdx.x;
    const int lane = tid & 31;
    const int wid  = tid >> 5;           // 0..7

    // ======================= IDX BLOCKS [0, 64) ============================
    if (bid < IDXB) {
        const int c = bid;
        const int t = c * CHTOK + tid;
        const unsigned lt = (1u << lane) - 1u;

        int4 m[4];
        #pragma unroll
        for (int i = 0; i < 4; i++) m[i] = hm4[(size_t)t * 4 + i];
        const int* v = (const int*)m;

        unsigned bits = 0;
        #pragma unroll
        for (int e = 0; e < N_EXP; e++) bits |= (v[e] > 0 ? 1u : 0u) << e;

        __shared__ int s_cnt[8][N_EXP];

        int      k = 0;
        int      e_sel[2] = {-1, -1};
        unsigned b_sel[2] = {0, 0};
        #pragma unroll
        for (int e = 0; e < N_EXP; e++) {
            unsigned ball = __ballot_sync(0xffffffffu, (bits >> e) & 1u);
            if (lane == 0) s_cnt[wid][e] = __popc(ball);
            if (((bits >> e) & 1u) && k < 2) { e_sel[k] = e; b_sel[k] = ball; k++; }
        }
        __syncthreads();

        if (tid < N_EXP) {
            int sum = 0;
            #pragma unroll
            for (int w = 0; w < 8; w++) sum += s_cnt[w][tid];
            g_cnt[tid * CHUNKS + c] = sum;
        }

        unsigned meta = 0xFFFFFFFFu;
        #pragma unroll
        for (int j = 0; j < 2; j++) {
            unsigned h = 0xFFFFu;
            if (j < k) {
                const int e = e_sel[j];
                int woff = 0;
                #pragma unroll
                for (int w = 0; w < 8; w++) if (w < wid) woff += s_cnt[w][e];
                const int rank = woff + __popc(b_sel[j] & lt);   // < 256
                h = ((unsigned)rank << 4) | (unsigned)e;
            }
            meta = (meta & ~(0xFFFFu << (16 * j))) | (h << (16 * j));
        }
        g_meta[t] = (int)meta;

        __threadfence();                  // publish before signaling
        __syncthreads();
        if (tid == 0) atomicAdd(&g_done, 1u);
    }
    // ======================= TOKEN BLOCKS [64, 64+T_TOK) ===================
    else if (bid < IDXB + T_TOK) {
        const int t = bid - IDXB;
        const int c = t >> 8;             // CHTOK = 256

        // Issue all independent loads BEFORE the flag check: the 8KB row
        // (streaming) and this token's 16 gate scores.
        const float4* __restrict__ r = in4 + (size_t)t * ROW4;
        float4 a = __ldcs(r + tid);
        float4 b = __ldcs(r + tid + 256);

        __shared__ float s_sc[N_EXP];
        __shared__ int   s_dst[2];
        __shared__ float s_g[2];
        if (tid < N_EXP) s_sc[tid] = __ldg(&score[t * N_EXP + tid]);

        // Wait for idx publication (wave-1 blocks: ~idx duration, hidden
        // under the loads above; later blocks: single check, already set).
        if (tid == 0) {
            volatile unsigned* p = &g_done;
            while (*p < IDXB) __nanosleep(100);
        }
        __syncthreads();                  // also publishes s_sc

        const int meta = (tid < 64) ? __ldcg(&g_meta[t]) : 0;
        if (tid < 64) {
            const int j  = tid >> 5;      // assignment 0 / 1
            const int ln = tid & 31;
            const unsigned h = ((unsigned)meta >> (16 * j)) & 0xFFFFu;
            int   dst = -1;
            float g   = 0.0f;
            if (h != 0xFFFFu) {
                const int e    = (int)(h & 15u);
                const int rank = (int)(h >> 4);
                int part = 0;
                if (ln < c)      part += __ldcg(&g_cnt[e * CHUNKS + ln]);
                if (ln + 32 < c) part += __ldcg(&g_cnt[e * CHUNKS + ln + 32]);
                #pragma unroll
                for (int o = 16; o >= 1; o >>= 1)
                    part += __shfl_down_sync(0xffffffffu, part, o);
                if (ln == 0) {
                    const int pos = part + rank;
                    if (pos < CAP) dst = e * CAP + pos;
                    g = s_sc[e];
                }
            }
            if (ln == 0) { s_dst[j] = dst; s_g[j] = g; }
        }
        __syncthreads();

        const int   d0 = s_dst[0];
        const int   d1 = s_dst[1];
        const float g0 = s_g[0];
        const float g1 = s_g[1];

        if (d0 >= 0) {
            float4* o = out4 + (size_t)d0 * ROW4;
            __stcs(o + tid,       make_float4(a.x * g0, a.y * g0, a.z * g0, a.w * g0));
            __stcs(o + tid + 256, make_float4(b.x * g0, b.y * g0, b.z * g0, b.w * g0));
        }
        if (d1 >= 0) {
            float4* o = out4 + (size_t)d1 * ROW4;
            __stcs(o + tid,       make_float4(a.x * g1, a.y * g1, a.z * g1, a.w * g1));
            __stcs(o + tid + 256, make_float4(b.x * g1, b.y * g1, b.z * g1, b.w * g1));
        }
    }
    // ======================= FILL BLOCKS (last 128) ========================
    else {
        const int f = bid - IDXB - T_TOK;
        const int e = f >> 3;
        const int y = f & 7;

        if (tid == 0) {
            volatile unsigned* p = &g_done;
            while (*p < IDXB) __nanosleep(100);
        }
        __syncthreads();

        __shared__ int s_load;
        if (tid < 32) {
            int part = __ldcg(&g_cnt[e * CHUNKS + tid]) +
                       __ldcg(&g_cnt[e * CHUNKS + tid + 32]);
            #pragma unroll
            for (int o = 16; o >= 1; o >>= 1)
                part += __shfl_down_sync(0xffffffffu, part, o);
            if (tid == 0) {
                const int load = part < CAP ? part : CAP;
                s_load = load;
                if (y == 0 && out_size >= (long long)(OUT_MAIN + N_EXP))
                    out[OUT_MAIN + e] = (float)load;
            }
        }
        __syncthreads();
        const int load = s_load;
        const float4 z = make_float4(0.f, 0.f, 0.f, 0.f);
        for (int r = load + y; r < CAP; r += 8) {
            float4* o = out4 + (size_t)(e * CAP + r) * ROW4;
            __stcs(o + tid, z);
            __stcs(o + tid + 256, z);
        }
    }

    // ======================= REPLAY-SAFE RESET =============================
    // Every block arrives here exactly once, after it is past its flag check.
    // The last arriver resets both counters for the next graph replay; no
    // block can still be spinning on g_done at that point.
    __syncthreads();
    if (tid == 0) {
        const unsigned prev = atomicAdd(&g_fin, 1u);
        if (prev == GRID_T - 1) {
            g_done = 0u;
            __threadfence();
            g_fin = 0u;
        }
    }
}

extern "C" void kernel_launch(void* const* d_in, const int* in_sizes, int n_in,
                              void* d_out, int out_size)
{
    const float* in_flow  = (const float*)d_in[0];   // [T, D] f32
    const int*   hot_mask = (const int*)  d_in[1];   // [T, E] i32
    const float* score    = (const float*)d_in[2];   // [T, E] f32
    float*       out      = (float*)d_out;

    moe_kernel<<<GRID_T, 256>>>((const float4*)in_flow, score,
                                (const int4*)hot_mask,
                                (float4*)out, out, (long long)out_size);
}